// round 10
// baseline (speedup 1.0000x reference)
#include <cuda_runtime.h>

// Permutation: out[b,i,j,W,p,q] = x[b, 2i+p, 2j+q, W]   (k=2 unfold repack)
// x: (16, 64, 224, 224) fp32 -> pure streaming permutation, HBM-bound.
//
// R10 = R9 (8 segments/block, 448 threads, XOR-swizzled conflict-free smem,
// LDG.128 in / STG.128 out, streaming hints) + __launch_bounds__(448, 4):
// forces regs <= 36 so 4 blocks/SM are resident (1792 threads, 87% occ)
// instead of R9's register-limited 3 blocks/SM (61% occ).

#define H 224
#define W_DIM 224
#define C 64
#define JN 112          // h/2
#define IN 32           // c/2
#define W4 56           // W_DIM/4 float4 per row
#define SEGB 8          // segments per block
#define THREADS 448     // SEGB * W4
#define GRID 7168       // 57344 / SEGB

__device__ __forceinline__ int sw(int f) { return f ^ ((f >> 3) & 7); }

__global__ void __launch_bounds__(THREADS, 4) KernelActivation_perm10(
    const float4* __restrict__ x4, float4* __restrict__ out4)
{
    __shared__ float4 s[SEGB * W_DIM];   // 28672 B

    const int tid  = threadIdx.x;
    const int sl   = tid / W4;           // 0..7 local segment
    const int wg   = tid % W4;           // 0..55 float4 group in row
    const int seg0 = blockIdx.x * SEGB;
    const int seg  = seg0 + sl;

    const int j = seg % JN;
    const int t = seg / JN;
    const int i = t & (IN - 1);
    const int b = t >> 5;

    // x[b, 2i+p, 2j+q, :] rows (float4 units)
    const int base = ((b * C + 2 * i) * H + 2 * j) * W4 + wg;

    const float4 r00 = __ldcs(&x4[base]);                 // p=0 q=0
    const float4 r01 = __ldcs(&x4[base + W4]);            // p=0 q=1
    const float4 r10 = __ldcs(&x4[base + H * W4]);        // p=1 q=0
    const float4 r11 = __ldcs(&x4[base + H * W4 + W4]);   // p=1 q=1

    // STS: f = 4*tid + m, swizzled -> conflict-free
    const int f0 = 4 * tid;
    s[sw(f0 + 0)] = make_float4(r00.x, r01.x, r10.x, r11.x);
    s[sw(f0 + 1)] = make_float4(r00.y, r01.y, r10.y, r11.y);
    s[sw(f0 + 2)] = make_float4(r00.z, r01.z, r10.z, r11.z);
    s[sw(f0 + 3)] = make_float4(r00.w, r01.w, r10.w, r11.w);

    __syncthreads();

    // drain: contiguous 28672B block store, LDS swizzled -> conflict-free
    float4* dst = &out4[(long)seg0 * W_DIM];
#pragma unroll
    for (int m = 0; m < 4; m++) {
        const int f = m * THREADS + tid;
        __stcs(&dst[f], s[sw(f)]);
    }
}

extern "C" void kernel_launch(void* const* d_in, const int* in_sizes, int n_in,
                              void* d_out, int out_size)
{
    const float4* x4 = (const float4*)d_in[0];
    float4* out4 = (float4*)d_out;
    KernelActivation_perm10<<<GRID, THREADS>>>(x4, out4);
}

// round 11
// speedup vs baseline: 1.0015x; 1.0015x over previous
#include <cuda_runtime.h>

// Permutation: out[b,i,j,W,p,q] = x[b, 2i+p, 2j+q, W]   (k=2 unfold repack)
// x: (16, 64, 224, 224) fp32 -> pure streaming permutation, HBM-bound.
//
// R11 = R9 (best wall: 8 segments/block, 448 threads, XOR-swizzled
// conflict-free smem, LDG.128 in / STG.128 out, streaming hints)
// + L2::256B prefetch qualifier on the loads: each L2 miss pulls a 256B
// DRAM burst instead of 128B. Reads are perfectly dense, so every
// prefetched byte is consumed by a neighboring warp; read request count
// at the DRAM scheduler halves -> fewer R/W bus turnarounds.

#define H 224
#define W_DIM 224
#define C 64
#define JN 112          // h/2
#define IN 32           // c/2
#define W4 56           // W_DIM/4 float4 per row
#define SEGB 8          // segments per block
#define THREADS 448     // SEGB * W4
#define GRID 7168       // 57344 / SEGB

__device__ __forceinline__ int sw(int f) { return f ^ ((f >> 3) & 7); }

__device__ __forceinline__ float4 ldcs_256(const float4* p) {
    float4 v;
    asm volatile("ld.global.cs.L2::256B.v4.f32 {%0, %1, %2, %3}, [%4];"
                 : "=f"(v.x), "=f"(v.y), "=f"(v.z), "=f"(v.w)
                 : "l"(p));
    return v;
}

__global__ void __launch_bounds__(THREADS) KernelActivation_perm11(
    const float4* __restrict__ x4, float4* __restrict__ out4)
{
    __shared__ float4 s[SEGB * W_DIM];   // 28672 B

    const int tid  = threadIdx.x;
    const int sl   = tid / W4;           // 0..7 local segment
    const int wg   = tid % W4;           // 0..55 float4 group in row
    const int seg0 = blockIdx.x * SEGB;
    const int seg  = seg0 + sl;

    const int j = seg % JN;
    const int t = seg / JN;
    const int i = t & (IN - 1);
    const int b = t >> 5;

    // x[b, 2i+p, 2j+q, :] rows (float4 units)
    const int base = ((b * C + 2 * i) * H + 2 * j) * W4 + wg;

    const float4 r00 = ldcs_256(&x4[base]);                 // p=0 q=0
    const float4 r01 = ldcs_256(&x4[base + W4]);            // p=0 q=1
    const float4 r10 = ldcs_256(&x4[base + H * W4]);        // p=1 q=0
    const float4 r11 = ldcs_256(&x4[base + H * W4 + W4]);   // p=1 q=1

    // STS: f = 4*tid + m, swizzled -> conflict-free
    const int f0 = 4 * tid;
    s[sw(f0 + 0)] = make_float4(r00.x, r01.x, r10.x, r11.x);
    s[sw(f0 + 1)] = make_float4(r00.y, r01.y, r10.y, r11.y);
    s[sw(f0 + 2)] = make_float4(r00.z, r01.z, r10.z, r11.z);
    s[sw(f0 + 3)] = make_float4(r00.w, r01.w, r10.w, r11.w);

    __syncthreads();

    // drain: contiguous 28672B block store, LDS swizzled -> conflict-free
    float4* dst = &out4[(long)seg0 * W_DIM];
#pragma unroll
    for (int m = 0; m < 4; m++) {
        const int f = m * THREADS + tid;
        __stcs(&dst[f], s[sw(f)]);
    }
}

extern "C" void kernel_launch(void* const* d_in, const int* in_sizes, int n_in,
                              void* d_out, int out_size)
{
    const float4* x4 = (const float4*)d_in[0];
    float4* out4 = (float4*)d_out;
    KernelActivation_perm11<<<GRID, THREADS>>>(x4, out4);
}

// round 12
// speedup vs baseline: 1.0045x; 1.0030x over previous
#include <cuda_runtime.h>

// Permutation: out[b,i,j,W,p,q] = x[b, 2i+p, 2j+q, W]   (k=2 unfold repack)
// x: (16, 64, 224, 224) fp32 -> pure streaming permutation, HBM-bound.
//
// FINAL (= R9, confirm re-bench): best wall of an 11-variant series that
// converged at the B300 1:1 read/write HBM ceiling (~79% dram active).
//  - 8 segments per block, 448 threads, one-shot grid of 7168 blocks
//  - loads : 4x LDG.128 per thread, 512B contiguous per warp, __ldcs
//  - smem  : XOR swizzle g(f) = f ^ ((f>>3)&7) (float4 units) ->
//            conflict-free for BOTH the stride-4 STS interleave and
//            the stride-1 LDS drain
//  - stores: contiguous 28672B run per block, STG.128 + __stcs
// Variants tested and rejected: TMA bulk in/out (DRAM +1%, wall neutral,
// occupancy/tail costs), persistent grid (wave imbalance), default
// write-back stores, L2::256B burst hints, forced 4-block residency.

#define H 224
#define W_DIM 224
#define C 64
#define JN 112          // h/2
#define IN 32           // c/2
#define W4 56           // W_DIM/4 float4 per row
#define SEGB 8          // segments per block
#define THREADS 448     // SEGB * W4
#define GRID 7168       // 57344 / SEGB

__device__ __forceinline__ int sw(int f) { return f ^ ((f >> 3) & 7); }

__global__ void __launch_bounds__(THREADS) KernelActivation_final(
    const float4* __restrict__ x4, float4* __restrict__ out4)
{
    __shared__ float4 s[SEGB * W_DIM];   // 28672 B

    const int tid  = threadIdx.x;
    const int sl   = tid / W4;           // 0..7 local segment
    const int wg   = tid % W4;           // 0..55 float4 group in row
    const int seg0 = blockIdx.x * SEGB;
    const int seg  = seg0 + sl;

    const int j = seg % JN;
    const int t = seg / JN;
    const int i = t & (IN - 1);
    const int b = t >> 5;

    // x[b, 2i+p, 2j+q, :] rows (float4 units)
    const int base = ((b * C + 2 * i) * H + 2 * j) * W4 + wg;

    const float4 r00 = __ldcs(&x4[base]);                 // p=0 q=0
    const float4 r01 = __ldcs(&x4[base + W4]);            // p=0 q=1
    const float4 r10 = __ldcs(&x4[base + H * W4]);        // p=1 q=0
    const float4 r11 = __ldcs(&x4[base + H * W4 + W4]);   // p=1 q=1

    // STS: f = 4*tid + m, swizzled -> conflict-free
    const int f0 = 4 * tid;
    s[sw(f0 + 0)] = make_float4(r00.x, r01.x, r10.x, r11.x);
    s[sw(f0 + 1)] = make_float4(r00.y, r01.y, r10.y, r11.y);
    s[sw(f0 + 2)] = make_float4(r00.z, r01.z, r10.z, r11.z);
    s[sw(f0 + 3)] = make_float4(r00.w, r01.w, r10.w, r11.w);

    __syncthreads();

    // drain: contiguous 28672B block store, LDS swizzled -> conflict-free
    float4* dst = &out4[(long)seg0 * W_DIM];
#pragma unroll
    for (int m = 0; m < 4; m++) {
        const int f = m * THREADS + tid;
        __stcs(&dst[f], s[sw(f)]);
    }
}

extern "C" void kernel_launch(void* const* d_in, const int* in_sizes, int n_in,
                              void* d_out, int out_size)
{
    const float4* x4 = (const float4*)d_in[0];
    float4* out4 = (float4*)d_out;
    KernelActivation_final<<<GRID, THREADS>>>(x4, out4);
}